// round 1
// baseline (speedup 1.0000x reference)
#include <cuda_runtime.h>

// Net_24395414241687 — two-layer NNConv GNN + readout, ending in
// log_softmax over axis=1 of a [G, 1] tensor.
//
// log_softmax of a length-1 axis is identically zero:
//   log_softmax(x)[i] = x - logsumexp(x) = x - x = 0   (bit-exact in the
//   max-subtracted formulation JAX uses; all upstream values are finite).
//
// Therefore the reference output is exactly zeros([G, 1]) for EVERY input,
// and the entire GNN pipeline is dead code w.r.t. the output. The optimal
// kernel is a single launch zero-filling d_out (which the harness poisons
// to 0xAA before timing, so the write is mandatory).

__global__ void net_zero_out_kernel(float* __restrict__ out, int n) {
    int i = blockIdx.x * blockDim.x + threadIdx.x;
    if (i < n) out[i] = 0.0f;
}

extern "C" void kernel_launch(void* const* d_in, const int* in_sizes, int n_in,
                              void* d_out, int out_size) {
    (void)d_in; (void)in_sizes; (void)n_in;
    float* out = (float*)d_out;
    int threads = 256;
    int blocks = (out_size + threads - 1) / threads;
    net_zero_out_kernel<<<blocks, threads>>>(out, out_size);
}

// round 2
// speedup vs baseline: 1.2358x; 1.2358x over previous
#include <cuda_runtime.h>

// Net_24395414241687 — two-layer NNConv GNN + readout, ending in
// log_softmax over axis=1 of a [G, 1] tensor.
//
// log_softmax over a length-1 axis is identically zero (x - logsumexp(x)
// = x - x = 0, bit-exact in JAX's max-subtracted formulation; all upstream
// values finite). The reference output is exactly zeros([1024, 1]) for every
// input, so the whole GNN pipeline is dead code w.r.t. the output.
//
// R1: kernel-based zero fill measured 3.4us kernel / 4.9us e2e — pure grid
// launch floor. R2: replace the kernel node with a cudaMemsetAsync node
// (graph-capturable, allocation-free). The memset path avoids the SM grid
// launch entirely; 0x00 fill is bit-identical to 0.0f.

extern "C" void kernel_launch(void* const* d_in, const int* in_sizes, int n_in,
                              void* d_out, int out_size) {
    (void)d_in; (void)in_sizes; (void)n_in;
    cudaMemsetAsync(d_out, 0, (size_t)out_size * sizeof(float), 0);
}